// round 7
// baseline (speedup 1.0000x reference)
#include <cuda_runtime.h>
#include <cuda_bf16.h>
#include <cstdint>

// ---------------------------------------------------------------------------
// WaveFDTD2D, temporal blocking K=4, 128 persistent CTAs x 512 threads.
// Neighbor-only sync (per-CTA monotonic counters). SMEM rotation carries own
// rows; only halos reload from L2. Substeps use explicit two-phase
// load-all-then-compute so LDS latency is paid once per substep (manual MLP).
// ---------------------------------------------------------------------------

#define NX      512
#define NZ      512
#define NSTEPS  512
#define NREC    128
#define KST     4
#define NBLK    (NSTEPS / KST)     // 128
#define NCTA    128
#define NTHR    512
#define RROWS   4
#define EXT     12                 // RROWS + 2*KST
#define SROW    520
#define BUF     (EXT * SROW)
#define SMEM_FLOATS (4 * BUF)      // A,B,C,Coeff
#define SMEM_BYTES  (SMEM_FLOATS * 4)
#define PAD     32                 // 256B between counters

__device__ __align__(16) float g_P[2][NX * NZ];
__device__ __align__(16) float g_Q[2][NX * NZ];
__device__ unsigned long long g_done[NCTA * PAD];   // monotonic, never reset

static __device__ __forceinline__ void signal_done(int bid) {
    // bar.sync (caller) + release-reduction publishes all CTA stores
    asm volatile("red.add.release.gpu.u64 [%0], 1;"
                 :: "l"(&g_done[bid * PAD]) : "memory");
}

static __device__ __forceinline__ void wait_neighbors(int bid, unsigned long long tgt) {
    const unsigned long long* lo =
        (bid > 0) ? &g_done[(bid - 1) * PAD] : nullptr;
    const unsigned long long* hi =
        (bid < NCTA - 1) ? &g_done[(bid + 1) * PAD] : nullptr;
    bool need_lo = (lo != nullptr), need_hi = (hi != nullptr);
    while (need_lo || need_hi) {
        unsigned long long a = tgt, b = tgt;
        if (need_lo)
            asm volatile("ld.acquire.gpu.u64 %0, [%1];" : "=l"(a) : "l"(lo) : "memory");
        if (need_hi)
            asm volatile("ld.acquire.gpu.u64 %0, [%1];" : "=l"(b) : "l"(hi) : "memory");
        if (a >= tgt) need_lo = false;
        if (b >= tgt) need_hi = false;
    }
}

// Two-phase stencil substep over SMEM rows [LO,HI] (compile-time bounds).
// Phase 1 issues ALL loads for this thread's rows; phase 2 computes+stores.
template<int LO, int HI, bool STORE>
static __device__ __forceinline__ void substep(
    const float* __restrict__ Sl, const float* __restrict__ So,
    float* __restrict__ Sd, const float* __restrict__ Cc,
    int rlo, int rhi, int g0, int tx, int ty,
    int sx, int sz, const float* __restrict__ source, int t,
    float* __restrict__ gdst)
{
    constexpr int NIT = (HI - LO) / 4 + 1;
    const float INV  = 0.01f;    // 1/(dx*dz)
    const float DT2f = 1.0e-6f;  // dt^2
    const int colbase = 4 + tx * 4;

    float4 m[NIT], u[NIT], d[NIT], o[NIT], cf[NIT];
    float  lf[NIT], rg[NIT];
    bool   valid[NIT];

    // ---- phase 1: issue all SMEM loads back-to-back ----
    #pragma unroll
    for (int k = 0; k < NIT; ++k) {
        const int i = LO + ty + 4 * k;
        valid[k] = (i <= HI) && (i >= rlo) && (i <= rhi);
        const int base = i * SROW + colbase;
        if (valid[k]) {
            m[k]  = *reinterpret_cast<const float4*>(Sl + base);
            u[k]  = *reinterpret_cast<const float4*>(Sl + base - SROW);
            d[k]  = *reinterpret_cast<const float4*>(Sl + base + SROW);
            lf[k] = Sl[base - 1];
            rg[k] = Sl[base + 4];
            o[k]  = *reinterpret_cast<const float4*>(So + base);
            cf[k] = *reinterpret_cast<const float4*>(Cc + base);
        }
    }

    // ---- phase 2: compute + store ----
    #pragma unroll
    for (int k = 0; k < NIT; ++k) {
        if (!valid[k]) continue;
        const int i = LO + ty + 4 * k;
        const int base = i * SROW + colbase;
        float4 nw; float lap;
        lap  = ((((u[k].x + d[k].x) + lf[k])  + m[k].y) - 4.0f * m[k].x) * INV;
        nw.x = (2.0f * m[k].x - o[k].x) + cf[k].x * lap;
        lap  = ((((u[k].y + d[k].y) + m[k].x) + m[k].z) - 4.0f * m[k].y) * INV;
        nw.y = (2.0f * m[k].y - o[k].y) + cf[k].y * lap;
        lap  = ((((u[k].z + d[k].z) + m[k].y) + m[k].w) - 4.0f * m[k].z) * INV;
        nw.z = (2.0f * m[k].z - o[k].z) + cf[k].z * lap;
        lap  = ((((u[k].w + d[k].w) + m[k].z) + rg[k])  - 4.0f * m[k].w) * INV;
        nw.w = (2.0f * m[k].w - o[k].w) + cf[k].w * lap;
        const int g = g0 - 4 + i;
        if (g == sx && (sz >> 2) == tx) {
            reinterpret_cast<float*>(&nw)[sz & 3] += __ldg(source + t) * DT2f;
        }
        *reinterpret_cast<float4*>(Sd + base) = nw;
        if (STORE && i >= 4 && i <= 7) {
            __stcg(reinterpret_cast<float4*>(gdst + (size_t)g * NZ + tx * 4), nw);
        }
    }
}

__global__ void __launch_bounds__(NTHR, 1)
wave_fdtd_nb_kernel(const float* __restrict__ vel,
                    const float* __restrict__ source,
                    const int*   __restrict__ p_srcx,
                    const int*   __restrict__ p_srcz,
                    const int*   __restrict__ rec_x,
                    const int*   __restrict__ rec_z,
                    float*       __restrict__ out)
{
    extern __shared__ float sm[];
    __shared__ unsigned long long sm_base;
    float* Cc = sm + 3 * BUF;

    const int tid = threadIdx.x;
    const int bid = blockIdx.x;
    const int g0  = bid * RROWS;
    const int tx  = tid & 127;
    const int ty  = tid >> 7;    // 0..3

    const int sx = p_srcx[0];
    const int sz = p_srcz[0];

    // grid-edge clamps (identity for interior CTAs)
    const int clo = 4 - g0;        // min valid SMEM row
    const int chi = 515 - g0;      // max valid SMEM row

    int my_rx = -1, my_rz = 0;
    if (tid < NREC) { my_rx = __ldg(rec_x + tid); my_rz = __ldg(rec_z + tid); }
    const bool my_rec = (my_rx >= 0) && ((my_rx >> 2) == bid);
    const int  rec_off = my_rec ? ((4 + (my_rx & 3)) * SROW + 4 + my_rz) : 0;

    // ---- zero all SMEM; read own counter base ----
    for (int i = tid; i < SMEM_FLOATS; i += NTHR) sm[i] = 0.0f;
    if (tid == 0) sm_base = g_done[bid * PAD];
    __syncthreads();
    const unsigned long long base = sm_base;

    // ---- coefficients v^2*dt^2 into SMEM rows 1..10 ----
    const float DT2f = 1.0e-6f;
    for (int idx = tid; idx < 10 * 128; idx += NTHR) {
        const int r = 1 + (idx >> 7), c = idx & 127;
        const int g = g0 - 4 + r;
        if ((unsigned)g < (unsigned)NX) {
            const float4 v = __ldg(reinterpret_cast<const float4*>(
                                   vel + (size_t)g * NZ + c * 4));
            *reinterpret_cast<float4*>(Cc + r * SROW + 4 + c * 4) =
                make_float4(v.x * v.x * DT2f, v.y * v.y * DT2f,
                            v.z * v.z * DT2f, v.w * v.w * DT2f);
        }
    }

    // ---- zero OWN rows of global pair 0 ----
    {
        const float4 z = make_float4(0.f, 0.f, 0.f, 0.f);
        for (int idx = tid; idx < RROWS * 128; idx += NTHR) {
            const int r = idx >> 7, c = idx & 127;
            const size_t off = (size_t)(g0 + r) * NZ + c * 4;
            __stcg(reinterpret_cast<float4*>(g_P[0] + off), z);
            __stcg(reinterpret_cast<float4*>(g_Q[0] + off), z);
        }
    }
    __syncthreads();
    if (tid == 0) signal_done(bid);   // counter -> base+1

    // SMEM roles: A = p_n (Laplacian src), B = p_{n-1}, C = scratch
    float* A = sm;
    float* B = sm + BUF;
    float* C = sm + 2 * BUF;

    for (int b = 0; b < NBLK; ++b) {
        if (tid == 0)
            wait_neighbors(bid, base + 1 + (unsigned long long)b);
        __syncthreads();

        const int pb = b & 1;
        const float* gp = g_P[pb];
        const float* gq = g_Q[pb];

        // ---- load halos only: A rows {0..3, 8..11}, B rows {1,2,9,10} ----
        #pragma unroll
        for (int k = 0; k < 2; ++k) {
            const int idx = tid + k * NTHR;
            const int r0 = idx >> 7, c = idx & 127;
            const int r = (r0 < 4) ? r0 : r0 + 4;
            const int g = g0 - 4 + r;
            if ((unsigned)g < (unsigned)NX)
                *reinterpret_cast<float4*>(A + r * SROW + 4 + c * 4) =
                    __ldcg(reinterpret_cast<const float4*>(gp + (size_t)g * NZ + c * 4));
        }
        {
            const int r0 = tid >> 7, c = tid & 127;
            const int r = (r0 < 2) ? r0 + 1 : r0 + 7;   // 1,2,9,10
            const int g = g0 - 4 + r;
            if ((unsigned)g < (unsigned)NX)
                *reinterpret_cast<float4*>(B + r * SROW + 4 + c * 4) =
                    __ldcg(reinterpret_cast<const float4*>(gq + (size_t)g * NZ + c * 4));
        }
        __syncthreads();

        const int t0 = b * KST;
        float* gpo = g_P[pb ^ 1];
        float* gqo = g_Q[pb ^ 1];

        // s1: p_{n+1} = f(A, B) -> C, rows [1,10]
        substep<1, 10, false>(A, B, C, Cc, clo, chi, g0, tx, ty, sx, sz, source, t0, nullptr);
        __syncthreads();
        if (my_rec) out[(size_t)tid * NSTEPS + t0] = C[rec_off];

        // s2: p_{n+2} = f(C, A) -> B, rows [2,9]
        substep<2, 9, false>(C, A, B, Cc, clo, chi, g0, tx, ty, sx, sz, source, t0 + 1, nullptr);
        __syncthreads();
        if (my_rec) out[(size_t)tid * NSTEPS + t0 + 1] = B[rec_off];

        // s3: p_{n+3} = f(B, C) -> A, rows [3,8]; own rows -> Q[pb^1]
        substep<3, 8, true>(B, C, A, Cc, clo, chi, g0, tx, ty, sx, sz, source, t0 + 2, gqo);
        __syncthreads();
        if (my_rec) out[(size_t)tid * NSTEPS + t0 + 2] = A[rec_off];

        // s4: p_{n+4} = f(A, B) -> C, rows [4,7]; own rows -> P[pb^1]
        substep<4, 7, true>(A, B, C, Cc, clo, chi, g0, tx, ty, sx, sz, source, t0 + 3, gpo);
        __syncthreads();
        if (my_rec) out[(size_t)tid * NSTEPS + t0 + 3] = C[rec_off];

        if (tid == 0) signal_done(bid);   // counter -> base+2+b

        // rotate: A' = C (newest), B' = A, C' = B
        float* tmp = A; A = C; C = B; B = tmp;
    }
}

extern "C" void kernel_launch(void* const* d_in, const int* in_sizes, int n_in,
                              void* d_out, int out_size)
{
    const float* vel    = (const float*)d_in[0];
    const float* source = (const float*)d_in[1];
    const int*   srcx   = (const int*)d_in[2];
    const int*   srcz   = (const int*)d_in[3];
    const int*   rec_x  = (const int*)d_in[4];
    const int*   rec_z  = (const int*)d_in[5];
    float* out = (float*)d_out;

    cudaFuncSetAttribute(wave_fdtd_nb_kernel,
                         cudaFuncAttributeMaxDynamicSharedMemorySize, SMEM_BYTES);
    wave_fdtd_nb_kernel<<<NCTA, NTHR, SMEM_BYTES>>>(
        vel, source, srcx, srcz, rec_x, rec_z, out);
}

// round 8
// speedup vs baseline: 2.1550x; 2.1550x over previous
#include <cuda_runtime.h>
#include <cuda_bf16.h>
#include <cstdint>

// ---------------------------------------------------------------------------
// WaveFDTD2D, temporal blocking K=4, 128 persistent CTAs x 512 threads.
// Register-resident state: each thread owns rows {ty, ty+4, ty+8} x 4 cols for
// the WHOLE block; m (current), o (old), cf (v^2 dt^2) live in registers.
// SMEM holds only field images for neighbor (u/d/left/right) reads, 2 buffers
// ping-pong (4 substeps = even -> fixed roles). Neighbor-only sync.
// ---------------------------------------------------------------------------

#define NX      512
#define NZ      512
#define NSTEPS  512
#define NREC    128
#define KST     4
#define NBLK    (NSTEPS / KST)     // 128
#define NCTA    128
#define NTHR    512
#define RROWS   4
#define EXT     12                 // rows 0..11 in SMEM image
#define SROW    520
#define BUF     (EXT * SROW)
#define SMEM_FLOATS (2 * BUF)      // S0, S1
#define SMEM_BYTES  (SMEM_FLOATS * 4)
#define PAD     32

__device__ __align__(16) float g_P[2][NX * NZ];
__device__ __align__(16) float g_Q[2][NX * NZ];
__device__ unsigned long long g_done[NCTA * PAD];   // monotonic, never reset

static __device__ __forceinline__ void signal_done(int bid) {
    asm volatile("red.add.release.gpu.u64 [%0], 1;"
                 :: "l"(&g_done[bid * PAD]) : "memory");
}

static __device__ __forceinline__ void wait_neighbors(int bid, unsigned long long tgt) {
    const unsigned long long* lo =
        (bid > 0) ? &g_done[(bid - 1) * PAD] : nullptr;
    const unsigned long long* hi =
        (bid < NCTA - 1) ? &g_done[(bid + 1) * PAD] : nullptr;
    bool need_lo = (lo != nullptr), need_hi = (hi != nullptr);
    while (need_lo || need_hi) {
        unsigned long long a = tgt, b = tgt;
        if (need_lo)
            asm volatile("ld.acquire.gpu.u64 %0, [%1];" : "=l"(a) : "l"(lo) : "memory");
        if (need_hi)
            asm volatile("ld.acquire.gpu.u64 %0, [%1];" : "=l"(b) : "l"(hi) : "memory");
        if (a >= tgt) need_lo = false;
        if (b >= tgt) need_hi = false;
    }
}

// One substep over rows [LO,HI]. Reads neighbors from Scur, writes Snext.
// m/o updated in place (register state). Own rows (k==1) optionally STG'd.
template<int LO, int HI, bool STORE>
static __device__ __forceinline__ void substep(
    const float* __restrict__ Scur, float* __restrict__ Snext,
    float4 (&m)[3], float4 (&o)[3], const float4 (&cf)[3],
    int clo, int chi, int g0, int tx, int ty,
    int sx, int sz, const float* __restrict__ source, int t,
    float* __restrict__ gdst)
{
    const float INV  = 0.01f;    // 1/(dx*dz)
    const float DT2f = 1.0e-6f;  // dt^2
    const int colbase = 4 + tx * 4;
    #pragma unroll
    for (int k = 0; k < 3; ++k) {
        const int i = ty + 4 * k;
        if (i < LO || i > HI) continue;     // trapezoid (predicated on ty)
        if (i < clo || i > chi) continue;   // grid edge (CTA 0/127 only)
        const int base = i * SROW + colbase;
        const float4 u  = *reinterpret_cast<const float4*>(Scur + base - SROW);
        const float4 d  = *reinterpret_cast<const float4*>(Scur + base + SROW);
        const float  lf = Scur[base - 1];
        const float  rg = Scur[base + 4];
        float4 nw; float lap;
        lap  = ((((u.x + d.x) + lf)     + m[k].y) - 4.0f * m[k].x) * INV;
        nw.x = (2.0f * m[k].x - o[k].x) + cf[k].x * lap;
        lap  = ((((u.y + d.y) + m[k].x) + m[k].z) - 4.0f * m[k].y) * INV;
        nw.y = (2.0f * m[k].y - o[k].y) + cf[k].y * lap;
        lap  = ((((u.z + d.z) + m[k].y) + m[k].w) - 4.0f * m[k].z) * INV;
        nw.z = (2.0f * m[k].z - o[k].z) + cf[k].z * lap;
        lap  = ((((u.w + d.w) + m[k].z) + rg)     - 4.0f * m[k].w) * INV;
        nw.w = (2.0f * m[k].w - o[k].w) + cf[k].w * lap;
        const int g = g0 - 4 + i;
        if (g == sx && (sz >> 2) == tx) {
            const float sadd = __ldg(source + t) * DT2f;
            const int lane = sz & 3;
            nw.x += (lane == 0) ? sadd : 0.0f;
            nw.y += (lane == 1) ? sadd : 0.0f;
            nw.z += (lane == 2) ? sadd : 0.0f;
            nw.w += (lane == 3) ? sadd : 0.0f;
        }
        *reinterpret_cast<float4*>(Snext + base) = nw;
        if (STORE && k == 1) {
            __stcg(reinterpret_cast<float4*>(gdst + (size_t)g * NZ + tx * 4), nw);
        }
        o[k] = m[k];
        m[k] = nw;
    }
}

__global__ void __launch_bounds__(NTHR, 1)
wave_fdtd_reg_kernel(const float* __restrict__ vel,
                     const float* __restrict__ source,
                     const int*   __restrict__ p_srcx,
                     const int*   __restrict__ p_srcz,
                     const int*   __restrict__ rec_x,
                     const int*   __restrict__ rec_z,
                     float*       __restrict__ out)
{
    extern __shared__ float sm[];
    __shared__ unsigned long long sm_base;
    float* S0 = sm;           // holds p_n at block entry / p_{n+4} at exit
    float* S1 = sm + BUF;     // intermediate fields

    const int tid = threadIdx.x;
    const int bid = blockIdx.x;
    const int g0  = bid * RROWS;
    const int tx  = tid & 127;
    const int ty  = tid >> 7;    // 0..3
    const int colbase = 4 + tx * 4;

    const int sx = p_srcx[0];
    const int sz = p_srcz[0];

    const int clo = 4 - g0;        // min valid SMEM row (interior: <=0)
    const int chi = 515 - g0;      // max valid SMEM row (interior: >=11)

    int my_rx = -1, my_rz = 0;
    if (tid < NREC) { my_rx = __ldg(rec_x + tid); my_rz = __ldg(rec_z + tid); }
    const bool my_rec = (my_rx >= 0) && ((my_rx >> 2) == bid);
    const int  rec_off = my_rec ? ((4 + (my_rx & 3)) * SROW + 4 + my_rz) : 0;

    // ---- zero SMEM (halo rows/cols must be and stay zero); read counter ----
    for (int i = tid; i < SMEM_FLOATS; i += NTHR) sm[i] = 0.0f;
    if (tid == 0) sm_base = g_done[bid * PAD];
    __syncthreads();
    const unsigned long long base = sm_base;

    // ---- register state init ----
    const float DT2f = 1.0e-6f;
    float4 m[3], o[3], cf[3];
    #pragma unroll
    for (int k = 0; k < 3; ++k) {
        m[k] = make_float4(0.f, 0.f, 0.f, 0.f);
        o[k] = make_float4(0.f, 0.f, 0.f, 0.f);
        const int i = ty + 4 * k;
        const int g = g0 - 4 + i;
        if ((unsigned)g < (unsigned)NX) {
            const float4 v = __ldg(reinterpret_cast<const float4*>(
                                   vel + (size_t)g * NZ + tx * 4));
            cf[k] = make_float4(v.x * v.x * DT2f, v.y * v.y * DT2f,
                                v.z * v.z * DT2f, v.w * v.w * DT2f);
        } else {
            cf[k] = make_float4(0.f, 0.f, 0.f, 0.f);
        }
    }

    // ---- zero OWN rows of global pair 0 (stale from prior replay) ----
    {
        const float4 z = make_float4(0.f, 0.f, 0.f, 0.f);
        #pragma unroll
        for (int k = 0; k < 1; ++k) { }   // (placeholder, keeps structure clear)
        for (int idx = tid; idx < RROWS * 128; idx += NTHR) {
            const int r = idx >> 7, c = idx & 127;
            const size_t off = (size_t)(g0 + r) * NZ + c * 4;
            __stcg(reinterpret_cast<float4*>(g_P[0] + off), z);
            __stcg(reinterpret_cast<float4*>(g_Q[0] + off), z);
        }
    }
    __syncthreads();
    if (tid == 0) signal_done(bid);   // counter -> base+1

    for (int b = 0; b < NBLK; ++b) {
        if (tid == 0)
            wait_neighbors(bid, base + 1 + (unsigned long long)b);
        __syncthreads();

        const int pb = b & 1;
        const float* gp = g_P[pb];
        const float* gq = g_Q[pb];

        // ---- halo refresh: rows k=0 (0..3) and k=2 (8..11) ----
        // m <- global p_n; S0 row image <- same; o <- reg(rows 3,8) / global(1,2,9,10)
        #pragma unroll
        for (int k = 0; k < 3; k += 2) {
            const int i = ty + 4 * k;
            const int g = g0 - 4 + i;
            if ((unsigned)g < (unsigned)NX) {
                const float4 v = __ldcg(reinterpret_cast<const float4*>(
                                        gp + (size_t)g * NZ + tx * 4));
                if (i == 3 || i == 8) {
                    o[k] = m[k];              // p_{n-1} computed here at prev s3
                } else if (i == 1 || i == 2 || i == 9 || i == 10) {
                    o[k] = __ldcg(reinterpret_cast<const float4*>(
                                  gq + (size_t)g * NZ + tx * 4));
                }
                m[k] = v;
                *reinterpret_cast<float4*>(S0 + i * SROW + colbase) = v;
            }
        }
        __syncthreads();

        const int t0 = b * KST;
        float* gpo = g_P[pb ^ 1];
        float* gqo = g_Q[pb ^ 1];

        // s1: p_{n+1}, rows [1,10], S0 -> S1
        substep<1, 10, false>(S0, S1, m, o, cf, clo, chi, g0, tx, ty,
                              sx, sz, source, t0, nullptr);
        __syncthreads();
        if (my_rec) out[(size_t)tid * NSTEPS + t0] = S1[rec_off];

        // s2: p_{n+2}, rows [2,9], S1 -> S0
        substep<2, 9, false>(S1, S0, m, o, cf, clo, chi, g0, tx, ty,
                             sx, sz, source, t0 + 1, nullptr);
        __syncthreads();
        if (my_rec) out[(size_t)tid * NSTEPS + t0 + 1] = S0[rec_off];

        // s3: p_{n+3}, rows [3,8], S0 -> S1; own rows -> Q[pb^1]
        substep<3, 8, true>(S0, S1, m, o, cf, clo, chi, g0, tx, ty,
                            sx, sz, source, t0 + 2, gqo);
        __syncthreads();
        if (my_rec) out[(size_t)tid * NSTEPS + t0 + 2] = S1[rec_off];

        // s4: p_{n+4}, rows [4,7], S1 -> S0; own rows -> P[pb^1]
        substep<4, 7, true>(S1, S0, m, o, cf, clo, chi, g0, tx, ty,
                            sx, sz, source, t0 + 3, gpo);
        __syncthreads();
        if (my_rec) out[(size_t)tid * NSTEPS + t0 + 3] = S0[rec_off];

        if (tid == 0) signal_done(bid);   // counter -> base+2+b
    }
}

extern "C" void kernel_launch(void* const* d_in, const int* in_sizes, int n_in,
                              void* d_out, int out_size)
{
    const float* vel    = (const float*)d_in[0];
    const float* source = (const float*)d_in[1];
    const int*   srcx   = (const int*)d_in[2];
    const int*   srcz   = (const int*)d_in[3];
    const int*   rec_x  = (const int*)d_in[4];
    const int*   rec_z  = (const int*)d_in[5];
    float* out = (float*)d_out;

    cudaFuncSetAttribute(wave_fdtd_reg_kernel,
                         cudaFuncAttributeMaxDynamicSharedMemorySize, SMEM_BYTES);
    wave_fdtd_reg_kernel<<<NCTA, NTHR, SMEM_BYTES>>>(
        vel, source, srcx, srcz, rec_x, rec_z, out);
}